// round 16
// baseline (speedup 1.0000x reference)
#include <cuda_runtime.h>
#include <cuda_fp16.h>
#include <cstdint>

// Problem constants
#define NCODES 1024
#define DIM    64
#define BSZ    16
#define TLEN   16384
#define NSAMP  (BSZ * TLEN)          // 262144
#define ZQ_ELEMS (BSZ * DIM * TLEN)  // 16777216

#define IDX_OFF  ZQ_ELEMS
#define SCAL_OFF (ZQ_ELEMS + NSAMP)

typedef unsigned long long u64;

// ---------------- device globals (no dynamic alloc allowed) ----------------
__device__ float    g_c_sq[NCODES];
__device__ int      g_flags[NCODES];
__device__ double   g_loss_arr[64];
__device__ float    g_zsq[NSAMP];
__device__ u64      g_best[NSAMP];
__device__ int      g_done[8192];        // per warp-tile arrival counters
// A fragments: [t16 tile (16384)][kstep 4][split 2][lane 32][4 u32] = 64MB
__device__ uint32_t g_afrag[(size_t)16384 * 4 * 2 * 32 * 4];
// B fragments: [group 2][nb 64][kstep 4][split 2][lane 32][2 u32] = 256KB
__device__ uint32_t g_bfrag[2 * 64 * 4 * 2 * 32 * 2];

// fp16 hi/lo split pack helpers
__device__ __forceinline__ void split_pair(float x, float y, uint32_t& hi, uint32_t& lo) {
    __half hx = __float2half_rn(x);
    __half hy = __float2half_rn(y);
    float  rx = x - __half2float(hx);
    float  ry = y - __half2float(hy);
    __half lx = __float2half_rn(rx);
    __half ly = __float2half_rn(ry);
    hi = (uint32_t)__half_as_ushort(hx) | ((uint32_t)__half_as_ushort(hy) << 16);
    lo = (uint32_t)__half_as_ushort(lx) | ((uint32_t)__half_as_ushort(ly) << 16);
}

// m16n8k16 row.col f32.f16.f16.f32
#define HMMA(d, a, b0, b1) \
    asm volatile("mma.sync.aligned.m16n8k16.row.col.f32.f16.f16.f32 " \
        "{%0,%1,%2,%3}, {%4,%5,%6,%7}, {%8,%9}, {%0,%1,%2,%3};" \
        : "+f"((d)[0]), "+f"((d)[1]), "+f"((d)[2]), "+f"((d)[3]) \
        : "r"((a)[0]), "r"((a)[1]), "r"((a)[2]), "r"((a)[3]), "r"(b0), "r"(b1))

// ---------------------------------------------------------------------------
// prep: c_sq (exact sequential rounding), codebook fp16 hi/lo B-fragments
//       (codes scaled by 512), zero flags + loss slots. 16 blocks x 64 threads.
// ---------------------------------------------------------------------------
__global__ void __launch_bounds__(64)
prep_codebook(const float* __restrict__ codebook) {
    int j = blockIdx.x * 64 + threadIdx.x;  // 0..1023, one code per thread
    const float* r = codebook + (size_t)j * DIM;
    float s = 0.f;
    #pragma unroll
    for (int k = 0; k < DIM; k++) {
        float c = r[k];
        s = __fadd_rn(s, __fmul_rn(c, c));
    }
    g_c_sq[j]  = s;
    g_flags[j] = 0;
    if (j < 64) g_loss_arr[j] = 0.0;

    int group = j >> 9;
    int nbl   = (j >> 3) & 63;
    int nin   = j & 7;
    uint32_t* base = g_bfrag + (size_t)group * 32768;
    for (int ks = 0; ks < 4; ks++) {
        for (int t = 0; t < 4; t++) {
            int lane = nin * 4 + t;
            int kd = ks * 16 + 2 * t;
            uint32_t h0, l0, h1, l1;
            split_pair(r[kd]     * 512.f, r[kd + 1] * 512.f, h0, l0);
            split_pair(r[kd + 8] * 512.f, r[kd + 9] * 512.f, h1, l1);
            uint32_t o_hi = ((uint32_t)(nbl * 4 + ks) * 2 + 0) * 64 + lane * 2;
            uint32_t o_lo = ((uint32_t)(nbl * 4 + ks) * 2 + 1) * 64 + lane * 2;
            base[o_hi]     = h0;
            base[o_hi + 1] = h1;
            base[o_lo]     = l0;
            base[o_lo + 1] = l1;
        }
    }
}

// ---------------------------------------------------------------------------
// dummy: no-op launch to align ncu's profiled launch (#4) onto vq_mma_kernel
// ---------------------------------------------------------------------------
__global__ void dummy_kernel() {}

// ---------------------------------------------------------------------------
// z split: fused single loop (load pair -> zsq sequential -> split -> smem).
// Block = 128 samples = 8 sample-tiles. zsq keeps strict k=0..63 order.
// Also zeroes g_best and the g_done counters.
// ---------------------------------------------------------------------------
__global__ void __launch_bounds__(128)
z_split_kernel(const float* __restrict__ z_e) {
    __shared__ uint32_t buf[8192];   // 8 tiles x 1024 u32 = 32KB
    const int tid = threadIdx.x;
    const int s   = blockIdx.x * 128 + tid;
    const int tl  = tid >> 4;        // local tile 0..7
    const int r   = tid & 15;        // row in tile
    const int b   = s / TLEN;
    const int t   = s % TLEN;

    if (tid < 4) g_done[blockIdx.x * 4 + tid] = 0;   // 2048 blocks x 4 = 8192

    const float* zp = z_e + (size_t)b * DIM * TLEN + t;
    const int rlo = (r < 8) ? 0 : 1;
    const int rl  = r & 7;

    float zsq = 0.f;
    #pragma unroll
    for (int m = 0; m < 32; m++) {
        float z0 = zp[(size_t)(2 * m)     * TLEN];
        float z1 = zp[(size_t)(2 * m + 1) * TLEN];
        zsq = __fadd_rn(zsq, __fmul_rn(z0, z0));
        zsq = __fadd_rn(zsq, __fmul_rn(z1, z1));
        uint32_t h, l;
        split_pair(z0, z1, h, l);
        int kd    = 2 * m;
        int ks    = kd >> 4;
        int rem   = kd & 15;
        int tt    = (rem & 7) >> 1;
        int hioff = (rem < 8) ? 0 : 2;
        int lane  = rl * 4 + tt;
        uint32_t bh = (((uint32_t)(tl * 4 + ks) * 2 + 0) * 32 + lane) * 4;
        uint32_t bl = (((uint32_t)(tl * 4 + ks) * 2 + 1) * 32 + lane) * 4;
        buf[bh + rlo + hioff] = h;
        buf[bl + rlo + hioff] = l;
    }
    g_zsq[s]  = zsq;
    g_best[s] = ~0ull;

    __syncthreads();
    uint4* dst = (uint4*)g_afrag + (size_t)blockIdx.x * 2048;
    const uint4* srcb = (const uint4*)buf;
    #pragma unroll
    for (int i = 0; i < 16; i++) dst[tid + i * 128] = srcb[tid + i * 128];
}

// ---------------------------------------------------------------------------
// Main kernel: HMMA fp16 3-pass distance GEMM + fused argmin + FUSED zq/idx/
// loss epilogue. PERSISTENT grid (74, 2); warps drift independently through
// sample-blocks (no intra-loop syncthreads), so the 2nd warp to finish a
// warp-tile runs the memory epilogue while sibling warps keep the tensor
// pipe fed.
// ---------------------------------------------------------------------------
#define VQ_SMEM (131072 + 2048)

__global__ void __launch_bounds__(512, 1)
vq_mma_kernel(const float* __restrict__ codebook,
              float* __restrict__ zq_out,
              float* __restrict__ out_idx_f) {
    extern __shared__ __align__(16) uint32_t sb[];   // [32768] B frags + 512 csq
    const int tid   = threadIdx.x;
    const int lane  = tid & 31;
    const int w     = tid >> 5;
    const int group = blockIdx.y;

    // stage B fragments (128KB) + csq (2KB) -- once per CTA
    {
        const uint4* src = (const uint4*)(g_bfrag + (size_t)group * 32768);
        uint4* dst = (uint4*)sb;
        #pragma unroll
        for (int i = 0; i < 16; i++) dst[tid + i * 512] = src[tid + i * 512];
        ((float*)(sb + 32768))[tid] = g_c_sq[group * 512 + tid];
    }
    __syncthreads();
    const float* csq_s = (const float*)(sb + 32768);

    for (int bx = blockIdx.x; bx < 512; bx += 74) {
        const int wt    = bx * 16 + w;    // warp-tile id (32 samples)
        const int sbase = wt * 32;

        // resident A fragments: [tile2][kstep4][split2][4]
        uint32_t A[2][4][2][4];
        #pragma unroll
        for (int tl = 0; tl < 2; tl++)
            #pragma unroll
            for (int ks = 0; ks < 4; ks++)
                #pragma unroll
                for (int sp = 0; sp < 2; sp++) {
                    const uint4* p = (const uint4*)g_afrag
                        + (((size_t)(wt * 2 + tl) * 4 + ks) * 2 + sp) * 32 + lane;
                    uint4 v = *p;
                    A[tl][ks][sp][0] = v.x; A[tl][ks][sp][1] = v.y;
                    A[tl][ks][sp][2] = v.z; A[tl][ks][sp][3] = v.w;
                }

        float zs[4];
        #pragma unroll
        for (int q = 0; q < 4; q++) zs[q] = g_zsq[sbase + (lane >> 2) + q * 8];

        float bv[4] = {3.4e38f, 3.4e38f, 3.4e38f, 3.4e38f};
        int   bi[4] = {0, 0, 0, 0};

        for (int nb = 0; nb < 64; nb++) {
            uint32_t B[4][2][2];
            #pragma unroll
            for (int ks = 0; ks < 4; ks++)
                #pragma unroll
                for (int sp = 0; sp < 2; sp++) {
                    uint2 t2 = *(const uint2*)(sb + ((nb * 4 + ks) * 2 + sp) * 64 + lane * 2);
                    B[ks][sp][0] = t2.x; B[ks][sp][1] = t2.y;
                }
            float2 cq = *(const float2*)(csq_s + nb * 8 + (lane & 3) * 2);

            float acc[2][4] = {{0.f, 0.f, 0.f, 0.f}, {0.f, 0.f, 0.f, 0.f}};
            #pragma unroll
            for (int tl = 0; tl < 2; tl++)
                #pragma unroll
                for (int ks = 0; ks < 4; ks++) {
                    HMMA(acc[tl], A[tl][ks][0], B[ks][0][0], B[ks][0][1]);  // zhi*chi
                    HMMA(acc[tl], A[tl][ks][1], B[ks][0][0], B[ks][0][1]);  // zlo*chi
                    HMMA(acc[tl], A[tl][ks][0], B[ks][1][0], B[ks][1][1]);  // zhi*clo
                }

            // dist = R( R(zsq+csq) - 2*dot ), dot = acc/512
            const int j0 = group * 512 + nb * 8 + (lane & 3) * 2;
            #pragma unroll
            for (int tl = 0; tl < 2; tl++)
                #pragma unroll
                for (int h = 0; h < 2; h++) {
                    int slot = tl * 2 + h;
                    float s0 = __fadd_rn(zs[slot], cq.x);
                    float s1 = __fadd_rn(zs[slot], cq.y);
                    float dA = fmaf(-0.00390625f, acc[tl][h * 2 + 0], s0);
                    float dB = fmaf(-0.00390625f, acc[tl][h * 2 + 1], s1);
                    if (dA < bv[slot]) { bv[slot] = dA; bi[slot] = j0; }
                    if (dB < bv[slot]) { bv[slot] = dB; bi[slot] = j0 + 1; }
                }
        }

        // cross-lane reduce over l%4 (lexicographic (val, idx) min) + publish
        #pragma unroll
        for (int slot = 0; slot < 4; slot++) {
            #pragma unroll
            for (int off = 1; off <= 2; off <<= 1) {
                float v  = __shfl_xor_sync(0xFFFFFFFF, bv[slot], off);
                int   id = __shfl_xor_sync(0xFFFFFFFF, bi[slot], off);
                if (v < bv[slot] || (v == bv[slot] && id < bi[slot])) {
                    bv[slot] = v; bi[slot] = id;
                }
            }
            if ((lane & 3) == 0) {
                int sample = sbase + (lane >> 2) + slot * 8;
                u64 packed = ((u64)__float_as_uint(bv[slot]) << 32) | (uint32_t)bi[slot];
                atomicMin(&g_best[sample], packed);
            }
        }

        // ---- fused epilogue: 2nd warp (across both groups) to finish wt ----
        __syncwarp();
        __threadfence();
        int arrived = 0;
        if (lane == 0) arrived = atomicAdd(&g_done[wt], 1);
        arrived = __shfl_sync(0xFFFFFFFF, arrived, 0);
        if (arrived == 1) {
            __threadfence();
            const int s   = sbase + lane;
            const int bb  = s / TLEN;
            const int tt2 = s % TLEN;
            u64 p = __ldcg(&g_best[s]);
            int   idx  = (int)(uint32_t)(p & 0xffffffffu);
            float dist = __uint_as_float((uint32_t)(p >> 32));

            out_idx_f[s] = (float)idx;
            g_flags[idx] = 1;

            float* ob = zq_out + (size_t)bb * DIM * TLEN;
            const float4* crow = (const float4*)(codebook + (size_t)idx * DIM);
            #pragma unroll
            for (int kc = 0; kc < 16; kc++) {
                float4 c4 = __ldg(crow + kc);
                const size_t base = (size_t)(kc * 4) * TLEN + tt2;
                ob[base]            = c4.x;
                ob[base + TLEN]     = c4.y;
                ob[base + 2 * TLEN] = c4.z;
                ob[base + 3 * TLEN] = c4.w;
            }

            double d = (double)dist;
            #pragma unroll
            for (int off = 16; off > 0; off >>= 1)
                d += __shfl_down_sync(0xFFFFFFFF, d, off);
            if (lane == 0) atomicAdd(&g_loss_arr[wt & 63], d);
        }
    }
}

// ---------------------------------------------------------------------------
// finalize: utilization + loss scalars (sums 64 loss slots).
// ---------------------------------------------------------------------------
__global__ void __launch_bounds__(1024)
finalize_kernel(float* __restrict__ out) {
    __shared__ int cnt[1024];
    __shared__ double ls[64];
    int tid = threadIdx.x;
    cnt[tid] = g_flags[tid];
    if (tid < 64) ls[tid] = g_loss_arr[tid];
    __syncthreads();
    for (int off = 512; off > 0; off >>= 1) {
        if (tid < off) cnt[tid] += cnt[tid + off];
        if (off <= 32 && tid < off) ls[tid] += ls[tid + off];
        __syncthreads();
    }
    if (tid == 0) {
        float m = (float)(ls[0] / (double)ZQ_ELEMS);
        out[SCAL_OFF + 0] = m + 0.25f * m;
        out[SCAL_OFF + 1] = m;
        out[SCAL_OFF + 2] = m;
        out[SCAL_OFF + 3] = (float)cnt[0] / (float)NCODES;
    }
}

// ---------------------------------------------------------------------------
extern "C" void kernel_launch(void* const* d_in, const int* in_sizes, int n_in,
                              void* d_out, int out_size) {
    const float* z_e      = (const float*)d_in[0];
    const float* codebook = (const float*)d_in[1];
    float* out = (float*)d_out;

    static bool attr_set = false;
    if (!attr_set) {
        cudaFuncSetAttribute(vq_mma_kernel,
                             cudaFuncAttributeMaxDynamicSharedMemorySize, VQ_SMEM);
        attr_set = true;
    }

    prep_codebook<<<16, 64>>>(codebook);             // launch 1
    dummy_kernel<<<1, 32>>>();                       // launch 2 (profiler alignment)
    z_split_kernel<<<NSAMP / 128, 128>>>(z_e);       // launch 3
    vq_mma_kernel<<<dim3(74, 2), 512, VQ_SMEM>>>(codebook, out, out + IDX_OFF);  // launch 4 <- ncu
    finalize_kernel<<<1, 1024>>>(out);               // launch 5
}

// round 17
// speedup vs baseline: 1.0563x; 1.0563x over previous
#include <cuda_runtime.h>
#include <cuda_fp16.h>
#include <cstdint>

// Problem constants
#define NCODES 1024
#define DIM    64
#define BSZ    16
#define TLEN   16384
#define NSAMP  (BSZ * TLEN)          // 262144
#define ZQ_ELEMS (BSZ * DIM * TLEN)  // 16777216

#define IDX_OFF  ZQ_ELEMS
#define SCAL_OFF (ZQ_ELEMS + NSAMP)

typedef unsigned long long u64;

// ---------------- device globals (no dynamic alloc allowed) ----------------
__device__ float    g_c_sq[NCODES];
__device__ int      g_flags[NCODES];
__device__ double   g_loss;
__device__ float    g_zsq[NSAMP];
__device__ u64      g_best[NSAMP];
// A fragments: [t16 tile (16384)][kstep 4][split 2][lane 32][4 u32] = 64MB
__device__ uint32_t g_afrag[(size_t)16384 * 4 * 2 * 32 * 4];
// B fragments: [group 2][nb 64][kstep 4][split 2][lane 32][2 u32] = 256KB
__device__ uint32_t g_bfrag[2 * 64 * 4 * 2 * 32 * 2];

// fp16 hi/lo split pack helpers
__device__ __forceinline__ void split_pair(float x, float y, uint32_t& hi, uint32_t& lo) {
    __half hx = __float2half_rn(x);
    __half hy = __float2half_rn(y);
    float  rx = x - __half2float(hx);
    float  ry = y - __half2float(hy);
    __half lx = __float2half_rn(rx);
    __half ly = __float2half_rn(ry);
    hi = (uint32_t)__half_as_ushort(hx) | ((uint32_t)__half_as_ushort(hy) << 16);
    lo = (uint32_t)__half_as_ushort(lx) | ((uint32_t)__half_as_ushort(ly) << 16);
}

// m16n8k16 row.col f32.f16.f16.f32
#define HMMA(d, a, b0, b1) \
    asm volatile("mma.sync.aligned.m16n8k16.row.col.f32.f16.f16.f32 " \
        "{%0,%1,%2,%3}, {%4,%5,%6,%7}, {%8,%9}, {%0,%1,%2,%3};" \
        : "+f"((d)[0]), "+f"((d)[1]), "+f"((d)[2]), "+f"((d)[3]) \
        : "r"((a)[0]), "r"((a)[1]), "r"((a)[2]), "r"((a)[3]), "r"(b0), "r"(b1))

// ---------------------------------------------------------------------------
// prep: c_sq (exact sequential rounding), codebook fp16 hi/lo B-fragments
//       (codes scaled by 512), zero flags + loss. 16 blocks x 64 threads.
// ---------------------------------------------------------------------------
__global__ void __launch_bounds__(64)
prep_codebook(const float* __restrict__ codebook) {
    int j = blockIdx.x * 64 + threadIdx.x;  // 0..1023, one code per thread
    const float* r = codebook + (size_t)j * DIM;
    float s = 0.f;
    #pragma unroll
    for (int k = 0; k < DIM; k++) {
        float c = r[k];
        s = __fadd_rn(s, __fmul_rn(c, c));
    }
    g_c_sq[j]  = s;
    g_flags[j] = 0;
    if (j == 0) g_loss = 0.0;

    int group = j >> 9;
    int nbl   = (j >> 3) & 63;
    int nin   = j & 7;
    uint32_t* base = g_bfrag + (size_t)group * 32768;
    for (int ks = 0; ks < 4; ks++) {
        for (int t = 0; t < 4; t++) {
            int lane = nin * 4 + t;
            int kd = ks * 16 + 2 * t;
            uint32_t h0, l0, h1, l1;
            split_pair(r[kd]     * 512.f, r[kd + 1] * 512.f, h0, l0);
            split_pair(r[kd + 8] * 512.f, r[kd + 9] * 512.f, h1, l1);
            uint32_t o_hi = ((uint32_t)(nbl * 4 + ks) * 2 + 0) * 64 + lane * 2;
            uint32_t o_lo = ((uint32_t)(nbl * 4 + ks) * 2 + 1) * 64 + lane * 2;
            base[o_hi]     = h0;
            base[o_hi + 1] = h1;
            base[o_lo]     = l0;
            base[o_lo + 1] = l1;
        }
    }
}

// ---------------------------------------------------------------------------
// z split: fused single loop (load pair -> zsq sequential -> split -> smem).
// Block = 128 samples = 8 sample-tiles. zsq keeps strict k=0..63 order.
// ---------------------------------------------------------------------------
__global__ void __launch_bounds__(128)
z_split_kernel(const float* __restrict__ z_e) {
    __shared__ uint32_t buf[8192];   // 8 tiles x 1024 u32 = 32KB
    const int tid = threadIdx.x;
    const int s   = blockIdx.x * 128 + tid;
    const int tl  = tid >> 4;        // local tile 0..7
    const int r   = tid & 15;        // row in tile
    const int b   = s / TLEN;
    const int t   = s % TLEN;

    const float* zp = z_e + (size_t)b * DIM * TLEN + t;
    const int rlo = (r < 8) ? 0 : 1;
    const int rl  = r & 7;

    float zsq = 0.f;
    #pragma unroll
    for (int m = 0; m < 32; m++) {
        float z0 = zp[(size_t)(2 * m)     * TLEN];
        float z1 = zp[(size_t)(2 * m + 1) * TLEN];
        zsq = __fadd_rn(zsq, __fmul_rn(z0, z0));
        zsq = __fadd_rn(zsq, __fmul_rn(z1, z1));
        uint32_t h, l;
        split_pair(z0, z1, h, l);
        int kd    = 2 * m;
        int ks    = kd >> 4;
        int rem   = kd & 15;
        int tt    = (rem & 7) >> 1;
        int hioff = (rem < 8) ? 0 : 2;
        int lane  = rl * 4 + tt;
        uint32_t bh = (((uint32_t)(tl * 4 + ks) * 2 + 0) * 32 + lane) * 4;
        uint32_t bl = (((uint32_t)(tl * 4 + ks) * 2 + 1) * 32 + lane) * 4;
        buf[bh + rlo + hioff] = h;
        buf[bl + rlo + hioff] = l;
    }
    g_zsq[s]  = zsq;
    g_best[s] = ~0ull;

    __syncthreads();
    uint4* dst = (uint4*)g_afrag + (size_t)blockIdx.x * 2048;
    const uint4* srcb = (const uint4*)buf;
    #pragma unroll
    for (int i = 0; i < 16; i++) dst[tid + i * 128] = srcb[tid + i * 128];
}

// ---------------------------------------------------------------------------
// Main kernel: HMMA fp16 3-pass distance GEMM + fused argmin. PERSISTENT:
// grid (74, 2) = 148 CTAs; B fragments staged once per CTA.
// (R13/R15 version, byte-identical)
// ---------------------------------------------------------------------------
#define VQ_SMEM (131072 + 2048)

__global__ void __launch_bounds__(512, 1)
vq_mma_kernel() {
    extern __shared__ __align__(16) uint32_t sb[];   // [32768] B frags + 512 csq
    const int tid   = threadIdx.x;
    const int lane  = tid & 31;
    const int w     = tid >> 5;
    const int group = blockIdx.y;

    // stage B fragments (128KB) + csq (2KB) -- once per CTA
    {
        const uint4* src = (const uint4*)(g_bfrag + (size_t)group * 32768);
        uint4* dst = (uint4*)sb;
        #pragma unroll
        for (int i = 0; i < 16; i++) dst[tid + i * 512] = src[tid + i * 512];
        ((float*)(sb + 32768))[tid] = g_c_sq[group * 512 + tid];
    }
    __syncthreads();
    const float* csq_s = (const float*)(sb + 32768);

    for (int bx = blockIdx.x; bx < 512; bx += 74) {
        const int wt    = bx * 16 + w;    // warp-tile id (32 samples)
        const int sbase = wt * 32;

        // resident A fragments: [tile2][kstep4][split2][4]
        uint32_t A[2][4][2][4];
        #pragma unroll
        for (int tl = 0; tl < 2; tl++)
            #pragma unroll
            for (int ks = 0; ks < 4; ks++)
                #pragma unroll
                for (int sp = 0; sp < 2; sp++) {
                    const uint4* p = (const uint4*)g_afrag
                        + (((size_t)(wt * 2 + tl) * 4 + ks) * 2 + sp) * 32 + lane;
                    uint4 v = *p;
                    A[tl][ks][sp][0] = v.x; A[tl][ks][sp][1] = v.y;
                    A[tl][ks][sp][2] = v.z; A[tl][ks][sp][3] = v.w;
                }

        float zs[4];
        #pragma unroll
        for (int q = 0; q < 4; q++) zs[q] = g_zsq[sbase + (lane >> 2) + q * 8];

        float bv[4] = {3.4e38f, 3.4e38f, 3.4e38f, 3.4e38f};
        int   bi[4] = {0, 0, 0, 0};

        for (int nb = 0; nb < 64; nb++) {
            uint32_t B[4][2][2];
            #pragma unroll
            for (int ks = 0; ks < 4; ks++)
                #pragma unroll
                for (int sp = 0; sp < 2; sp++) {
                    uint2 t2 = *(const uint2*)(sb + ((nb * 4 + ks) * 2 + sp) * 64 + lane * 2);
                    B[ks][sp][0] = t2.x; B[ks][sp][1] = t2.y;
                }
            float2 cq = *(const float2*)(csq_s + nb * 8 + (lane & 3) * 2);

            float acc[2][4] = {{0.f, 0.f, 0.f, 0.f}, {0.f, 0.f, 0.f, 0.f}};
            #pragma unroll
            for (int tl = 0; tl < 2; tl++)
                #pragma unroll
                for (int ks = 0; ks < 4; ks++) {
                    HMMA(acc[tl], A[tl][ks][0], B[ks][0][0], B[ks][0][1]);  // zhi*chi
                    HMMA(acc[tl], A[tl][ks][1], B[ks][0][0], B[ks][0][1]);  // zlo*chi
                    HMMA(acc[tl], A[tl][ks][0], B[ks][1][0], B[ks][1][1]);  // zhi*clo
                }

            // epilogue: dist = R( R(zsq+csq) - 2*dot ), dot = acc/512
            const int j0 = group * 512 + nb * 8 + (lane & 3) * 2;
            #pragma unroll
            for (int tl = 0; tl < 2; tl++)
                #pragma unroll
                for (int h = 0; h < 2; h++) {
                    int slot = tl * 2 + h;
                    float s0 = __fadd_rn(zs[slot], cq.x);
                    float s1 = __fadd_rn(zs[slot], cq.y);
                    float dA = fmaf(-0.00390625f, acc[tl][h * 2 + 0], s0);
                    float dB = fmaf(-0.00390625f, acc[tl][h * 2 + 1], s1);
                    if (dA < bv[slot]) { bv[slot] = dA; bi[slot] = j0; }
                    if (dB < bv[slot]) { bv[slot] = dB; bi[slot] = j0 + 1; }
                }
        }

        // cross-lane reduce over l%4 (lexicographic (val, idx) min)
        #pragma unroll
        for (int slot = 0; slot < 4; slot++) {
            #pragma unroll
            for (int off = 1; off <= 2; off <<= 1) {
                float v  = __shfl_xor_sync(0xFFFFFFFF, bv[slot], off);
                int   id = __shfl_xor_sync(0xFFFFFFFF, bi[slot], off);
                if (v < bv[slot] || (v == bv[slot] && id < bi[slot])) {
                    bv[slot] = v; bi[slot] = id;
                }
            }
            if ((lane & 3) == 0) {
                int sample = sbase + (lane >> 2) + slot * 8;
                u64 packed = ((u64)__float_as_uint(bv[slot]) << 32) | (uint32_t)bi[slot];
                atomicMin(&g_best[sample], packed);
            }
        }
    }
}

// ---------------------------------------------------------------------------
// zq/idx/loss kernel with WARP-COOPERATIVE codebook row staging.
// Per 256-sample block: read packed (dist, idx) once (loss = dist, exact);
// warps gather the 256 rows row-contiguously into padded smem (2 lines/row
// instead of 16 scattered); each thread then writes its sample's z_q row
// coalesced. grid (TLEN/256 = 64, BSZ), 256 threads, 3 CTAs/SM.
// ---------------------------------------------------------------------------
#define ZQL_SMEM (256 * 65 * 4)   // 66560 bytes, stride 65 floats (bank-safe)

__global__ void __launch_bounds__(256)
zq_loss_kernel(const float* __restrict__ codebook,
               float* __restrict__ zq_out,
               float* __restrict__ out_idx_f) {
    extern __shared__ float rows[];   // [256][65]
    __shared__ int    sidx[256];
    __shared__ double rs[256];

    const int b   = blockIdx.y;
    const int tid = threadIdx.x;
    const int t   = blockIdx.x * 256 + tid;

    const u64 p      = g_best[(size_t)b * TLEN + t];
    const int idx    = (int)(uint32_t)(p & 0xffffffffu);
    const float dist = __uint_as_float((uint32_t)(p >> 32));

    sidx[tid] = idx;
    out_idx_f[b * TLEN + t] = (float)idx;
    g_flags[idx] = 1;
    __syncthreads();

    // cooperative gather: each warp stages 32 rows; half-warp = one 256B row
    {
        const int w     = tid >> 5;
        const int lane  = tid & 31;
        const int half  = lane >> 4;     // 0/1: which of the 2 rows this iter
        const int chunk = lane & 15;     // float4 index within the row
        #pragma unroll
        for (int i = 0; i < 16; i++) {
            int r = w * 32 + i * 2 + half;
            int ridx = sidx[r];
            float4 v = __ldg((const float4*)(codebook + (size_t)ridx * DIM) + chunk);
            float* dst = rows + r * 65 + chunk * 4;
            dst[0] = v.x; dst[1] = v.y; dst[2] = v.z; dst[3] = v.w;
        }
    }
    __syncthreads();

    // coalesced z_q writes: thread owns sample t, reads its smem row
    {
        float* ob = zq_out + (size_t)b * DIM * TLEN;
        const float* myrow = rows + tid * 65;
        #pragma unroll
        for (int k = 0; k < 64; k++)
            ob[(size_t)k * TLEN + t] = myrow[k];
    }

    rs[tid] = (double)dist;
    __syncthreads();
    for (int off = 128; off > 0; off >>= 1) {
        if (tid < off) rs[tid] += rs[tid + off];
        __syncthreads();
    }
    if (tid == 0) atomicAdd(&g_loss, rs[0]);
}

__global__ void __launch_bounds__(1024)
finalize_kernel(float* __restrict__ out) {
    __shared__ int cnt[1024];
    int tid = threadIdx.x;
    cnt[tid] = g_flags[tid];
    __syncthreads();
    for (int off = 512; off > 0; off >>= 1) {
        if (tid < off) cnt[tid] += cnt[tid + off];
        __syncthreads();
    }
    if (tid == 0) {
        float m = (float)(g_loss / (double)ZQ_ELEMS);
        out[SCAL_OFF + 0] = m + 0.25f * m;
        out[SCAL_OFF + 1] = m;
        out[SCAL_OFF + 2] = m;
        out[SCAL_OFF + 3] = (float)cnt[0] / (float)NCODES;
    }
}

// ---------------------------------------------------------------------------
extern "C" void kernel_launch(void* const* d_in, const int* in_sizes, int n_in,
                              void* d_out, int out_size) {
    const float* z_e      = (const float*)d_in[0];
    const float* codebook = (const float*)d_in[1];
    float* out = (float*)d_out;

    static bool attr_set = false;
    if (!attr_set) {
        cudaFuncSetAttribute(vq_mma_kernel,
                             cudaFuncAttributeMaxDynamicSharedMemorySize, VQ_SMEM);
        cudaFuncSetAttribute(zq_loss_kernel,
                             cudaFuncAttributeMaxDynamicSharedMemorySize, ZQL_SMEM);
        attr_set = true;
    }

    prep_codebook<<<16, 64>>>(codebook);             // launch 1
    z_split_kernel<<<NSAMP / 128, 128>>>(z_e);       // launch 2
    vq_mma_kernel<<<dim3(74, 2), 512, VQ_SMEM>>>();  // launch 3 (persistent)
    zq_loss_kernel<<<dim3(64, BSZ), 256, ZQL_SMEM>>>(codebook, out, out + IDX_OFF);  // launch 4 <- ncu
    finalize_kernel<<<1, 1024>>>(out);               // launch 5
}